// round 2
// baseline (speedup 1.0000x reference)
#include <cuda_runtime.h>

// Problem constants (fixed by the reference).
#define BN 4096
#define DN 768
#define KN 60
#define NLOGITS 61   // [pos, 60 negs]

// Per-row loss scratch (no device allocation allowed -> __device__ global).
__device__ float g_row_loss[BN];

// One CTA per user row. 256 threads = 8 warps.
// Warp w computes logits j = w, w+8, ... < 61.
__global__ void __launch_bounds__(256, 8)
u2i_loss_kernel(const float* __restrict__ user_emb,
                const float* __restrict__ item_emb,
                const int*   __restrict__ neg_idx)
{
    __shared__ float su[DN];          // user row
    __shared__ float slog[NLOGITS];   // logits

    const int b    = blockIdx.x;
    const int tid  = threadIdx.x;
    const int warp = tid >> 5;
    const int lane = tid & 31;

    // Stage user row into smem with float4 loads (192 float4s, 256 threads).
    const float4* u4  = reinterpret_cast<const float4*>(user_emb + (size_t)b * DN);
    float4*       su4 = reinterpret_cast<float4*>(su);
    if (tid < DN / 4) su4[tid] = u4[tid];
    __syncthreads();

    // Each warp: full-D dot products for its subset of the 61 logits.
    for (int j = warp; j < NLOGITS; j += 8) {
        const int item = (j == 0) ? b : neg_idx[b * KN + (j - 1)];
        const float4* p4 = reinterpret_cast<const float4*>(item_emb + (size_t)item * DN);

        float acc = 0.0f;
        #pragma unroll
        for (int t = 0; t < DN / 128; ++t) {      // 6 iterations, 128 floats/warp each
            const float4 pv = __ldg(&p4[t * 32 + lane]);
            const float4 uv = su4[t * 32 + lane];
            acc = fmaf(pv.x, uv.x, acc);
            acc = fmaf(pv.y, uv.y, acc);
            acc = fmaf(pv.z, uv.z, acc);
            acc = fmaf(pv.w, uv.w, acc);
        }
        // Warp reduction.
        #pragma unroll
        for (int o = 16; o > 0; o >>= 1)
            acc += __shfl_xor_sync(0xffffffffu, acc, o);
        if (lane == 0) slog[j] = acc;
    }
    __syncthreads();

    // Stable logsumexp over 61 logits; loss = logZ - logit_pos.
    if (tid == 0) {
        float m = slog[0];
        #pragma unroll 1
        for (int j = 1; j < NLOGITS; ++j) m = fmaxf(m, slog[j]);
        float s = 0.0f;
        #pragma unroll 1
        for (int j = 0; j < NLOGITS; ++j) s += expf(slog[j] - m);
        g_row_loss[b] = logf(s) + m - slog[0];
    }
}

// Deterministic mean over the 4096 per-row losses.
__global__ void __launch_bounds__(1024)
reduce_mean_kernel(float* __restrict__ out)
{
    __shared__ float s[1024];
    const int tid = threadIdx.x;
    float a = 0.0f;
    #pragma unroll
    for (int i = tid; i < BN; i += 1024) a += g_row_loss[i];
    s[tid] = a;
    __syncthreads();
    #pragma unroll
    for (int st = 512; st > 0; st >>= 1) {
        if (tid < st) s[tid] += s[tid + st];
        __syncthreads();
    }
    if (tid == 0) out[0] = s[0] * (1.0f / (float)BN);
}

extern "C" void kernel_launch(void* const* d_in, const int* in_sizes, int n_in,
                              void* d_out, int out_size)
{
    const float* user_emb = (const float*)d_in[0];
    const float* item_emb = (const float*)d_in[1];
    const int*   neg_idx  = (const int*)d_in[2];
    float*       out      = (float*)d_out;

    u2i_loss_kernel<<<BN, 256>>>(user_emb, item_emb, neg_idx);
    reduce_mean_kernel<<<1, 1024>>>(out);
}

// round 3
// speedup vs baseline: 1.0335x; 1.0335x over previous
#include <cuda_runtime.h>
#include <cuda_bf16.h>

// Problem constants (fixed by the reference).
#define BN 4096
#define DN 768
#define KN 60
#define NLOGITS 61   // [pos, 60 negs]

// Scratch (__device__ globals: no allocation allowed).
__device__ __nv_bfloat16 g_item_bf16[BN * DN];   // 6.3 MB bf16 mirror of item table
__device__ float g_row_loss[BN];
__device__ int   g_ctr = 0;

// ---------------------------------------------------------------------------
// Prologue: fp32 item table -> bf16 mirror. 8 floats per thread.
// ---------------------------------------------------------------------------
__global__ void __launch_bounds__(256)
convert_items_kernel(const float* __restrict__ item_emb)
{
    const int i = blockIdx.x * blockDim.x + threadIdx.x;   // 0 .. BN*DN/8-1
    const float4* src = reinterpret_cast<const float4*>(item_emb);
    const float4 a = src[2 * i];
    const float4 b = src[2 * i + 1];

    __nv_bfloat162 r[4];
    r[0] = __floats2bfloat162_rn(a.x, a.y);
    r[1] = __floats2bfloat162_rn(a.z, a.w);
    r[2] = __floats2bfloat162_rn(b.x, b.y);
    r[3] = __floats2bfloat162_rn(b.z, b.w);
    reinterpret_cast<uint4*>(g_item_bf16)[i] = *reinterpret_cast<uint4*>(r);
}

// ---------------------------------------------------------------------------
// Main: one CTA per user row; 8 warps split the 61 logits; bf16 item gathers.
// Last-arriving CTA performs the deterministic mean reduction.
// ---------------------------------------------------------------------------
__global__ void __launch_bounds__(256, 8)
u2i_loss_kernel(const float* __restrict__ user_emb,
                const int*   __restrict__ neg_idx,
                float*       __restrict__ out)
{
    __shared__ float su[DN];          // user row (fp32)
    __shared__ float slog[64];        // logits (61 used)
    __shared__ int   s_last;

    const int b    = blockIdx.x;
    const int tid  = threadIdx.x;
    const int warp = tid >> 5;
    const int lane = tid & 31;

    // Stage user row (192 float4s).
    const float4* u4  = reinterpret_cast<const float4*>(user_emb + (size_t)b * DN);
    float4*       su4 = reinterpret_cast<float4*>(su);
    if (tid < DN / 4) su4[tid] = u4[tid];
    if (tid >= 61 && tid < 64) slog[tid] = -3.0e38f;   // pad for warp LSE
    __syncthreads();

    // Dot products: each warp handles logits j = warp, warp+8, ...
    for (int j = warp; j < NLOGITS; j += 8) {
        const int item = (j == 0) ? b : neg_idx[b * KN + (j - 1)];
        const uint4* p4 = reinterpret_cast<const uint4*>(g_item_bf16 + (size_t)item * DN);

        float acc = 0.0f;
        #pragma unroll
        for (int t = 0; t < 3; ++t) {                 // 3 x (32 lanes x 8 bf16) = 768
            const int idx = t * 32 + lane;
            const uint4 pv = __ldg(&p4[idx]);         // 8 bf16 item values
            const float4 uv0 = su4[2 * idx];
            const float4 uv1 = su4[2 * idx + 1];

            const float2 f0 = __bfloat1622float2(*reinterpret_cast<const __nv_bfloat162*>(&pv.x));
            const float2 f1 = __bfloat1622float2(*reinterpret_cast<const __nv_bfloat162*>(&pv.y));
            const float2 f2 = __bfloat1622float2(*reinterpret_cast<const __nv_bfloat162*>(&pv.z));
            const float2 f3 = __bfloat1622float2(*reinterpret_cast<const __nv_bfloat162*>(&pv.w));

            acc = fmaf(f0.x, uv0.x, acc);
            acc = fmaf(f0.y, uv0.y, acc);
            acc = fmaf(f1.x, uv0.z, acc);
            acc = fmaf(f1.y, uv0.w, acc);
            acc = fmaf(f2.x, uv1.x, acc);
            acc = fmaf(f2.y, uv1.y, acc);
            acc = fmaf(f3.x, uv1.z, acc);
            acc = fmaf(f3.y, uv1.w, acc);
        }
        #pragma unroll
        for (int o = 16; o > 0; o >>= 1)
            acc += __shfl_xor_sync(0xffffffffu, acc, o);
        if (lane == 0) slog[j] = acc;
    }
    __syncthreads();

    // Warp 0: stable logsumexp over 61 logits (2 per lane), loss to scratch,
    // then ticket so the last CTA can reduce.
    if (warp == 0) {
        const float l0 = slog[lane];
        const float l1 = slog[lane + 32];
        float m = fmaxf(l0, l1);
        #pragma unroll
        for (int o = 16; o > 0; o >>= 1)
            m = fmaxf(m, __shfl_xor_sync(0xffffffffu, m, o));
        float s = expf(l0 - m) + ((lane + 32 < NLOGITS) ? expf(l1 - m) : 0.0f);
        #pragma unroll
        for (int o = 16; o > 0; o >>= 1)
            s += __shfl_xor_sync(0xffffffffu, s, o);
        if (lane == 0) {
            g_row_loss[b] = logf(s) + m - slog[0];
            __threadfence();
            const int t = atomicAdd(&g_ctr, 1);
            s_last = (t == BN - 1);
        }
    }
    __syncthreads();

    // Last CTA: deterministic mean over all 4096 row losses.
    if (s_last) {
        __threadfence();                               // acquire row losses
        __shared__ float sred[256];
        float a = 0.0f;
        #pragma unroll
        for (int i = tid; i < BN; i += 256) a += g_row_loss[i];
        sred[tid] = a;
        __syncthreads();
        #pragma unroll
        for (int st = 128; st > 0; st >>= 1) {
            if (tid < st) sred[tid] += sred[tid + st];
            __syncthreads();
        }
        if (tid == 0) {
            out[0] = sred[0] * (1.0f / (float)BN);
            g_ctr = 0;                                 // reset for next graph replay
        }
    }
}

extern "C" void kernel_launch(void* const* d_in, const int* in_sizes, int n_in,
                              void* d_out, int out_size)
{
    const float* user_emb = (const float*)d_in[0];
    const float* item_emb = (const float*)d_in[1];
    const int*   neg_idx  = (const int*)d_in[2];
    float*       out      = (float*)d_out;

    convert_items_kernel<<<BN * DN / 8 / 256, 256>>>(item_emb);
    u2i_loss_kernel<<<BN, 256>>>(user_emb, neg_idx, out);
}

// round 4
// speedup vs baseline: 1.4827x; 1.4346x over previous
#include <cuda_runtime.h>
#include <cuda_bf16.h>

// Problem constants (fixed by the reference).
#define BN 4096
#define DN 768
#define KN 60
#define NLOGITS 61   // [pos, 60 negs]

// Scratch (__device__ globals: no allocation allowed).
__device__ __nv_bfloat16 g_item_bf16[BN * DN];   // 6.3 MB bf16 mirror of item table
__device__ float g_row_loss[BN];
__device__ int   g_ctr = 0;

// ---------------------------------------------------------------------------
// Prologue: fp32 item table -> bf16 mirror. 8 floats per thread.
// ---------------------------------------------------------------------------
__global__ void __launch_bounds__(256)
convert_items_kernel(const float* __restrict__ item_emb)
{
    const int i = blockIdx.x * blockDim.x + threadIdx.x;   // 0 .. BN*DN/8-1
    const float4* src = reinterpret_cast<const float4*>(item_emb);
    const float4 a = src[2 * i];
    const float4 b = src[2 * i + 1];

    __nv_bfloat162 r[4];
    r[0] = __floats2bfloat162_rn(a.x, a.y);
    r[1] = __floats2bfloat162_rn(a.z, a.w);
    r[2] = __floats2bfloat162_rn(b.x, b.y);
    r[3] = __floats2bfloat162_rn(b.z, b.w);
    reinterpret_cast<uint4*>(g_item_bf16)[i] = *reinterpret_cast<uint4*>(r);
}

// 8 bf16 (uint4) dot fp32x8 (two float4) accumulated into fp32.
__device__ __forceinline__ void dot8(float& acc, const uint4& pv,
                                     const float4& uv0, const float4& uv1)
{
    const float2 f0 = __bfloat1622float2(*reinterpret_cast<const __nv_bfloat162*>(&pv.x));
    const float2 f1 = __bfloat1622float2(*reinterpret_cast<const __nv_bfloat162*>(&pv.y));
    const float2 f2 = __bfloat1622float2(*reinterpret_cast<const __nv_bfloat162*>(&pv.z));
    const float2 f3 = __bfloat1622float2(*reinterpret_cast<const __nv_bfloat162*>(&pv.w));
    acc = fmaf(f0.x, uv0.x, acc);
    acc = fmaf(f0.y, uv0.y, acc);
    acc = fmaf(f1.x, uv0.z, acc);
    acc = fmaf(f1.y, uv0.w, acc);
    acc = fmaf(f2.x, uv1.x, acc);
    acc = fmaf(f2.y, uv1.y, acc);
    acc = fmaf(f3.x, uv1.z, acc);
    acc = fmaf(f3.y, uv1.w, acc);
}

// ---------------------------------------------------------------------------
// Main: one CTA per user row; 8 warps split the 61 logits.
// User row lives in REGISTERS (no smem in the hot loop); two logits per
// iteration for 6-deep load parallelism.
// ---------------------------------------------------------------------------
__global__ void __launch_bounds__(256, 3)
u2i_loss_kernel(const float* __restrict__ user_emb,
                const int*   __restrict__ neg_idx,
                float*       __restrict__ out)
{
    __shared__ float su[DN];
    __shared__ float slog[64];        // 61 used, rest padded with -inf
    __shared__ int   s_last;

    const int b    = blockIdx.x;
    const int tid  = threadIdx.x;
    const int warp = tid >> 5;
    const int lane = tid & 31;

    // Stage user row coalesced into smem once, then lift this lane's slice
    // into registers (6 x float4 = 24 regs).
    const float4* u4  = reinterpret_cast<const float4*>(user_emb + (size_t)b * DN);
    float4*       su4 = reinterpret_cast<float4*>(su);
    if (tid < DN / 4) su4[tid] = u4[tid];
    if (tid >= 61 && tid < 64) slog[tid] = -3.0e38f;
    __syncthreads();

    float4 uv[6];
    #pragma unroll
    for (int t = 0; t < 3; ++t) {
        uv[2 * t]     = su4[2 * (t * 32 + lane)];
        uv[2 * t + 1] = su4[2 * (t * 32 + lane) + 1];
    }

    // Logit pairs (j, j+8): warps 0-4 do 4 pairs, warps 5-7 do 3 pairs + 1.
    for (int j = warp; j < NLOGITS; j += 16) {
        const int  j2   = j + 8;
        const bool has2 = (j2 < NLOGITS);

        const int it0 = (j == 0) ? b : neg_idx[b * KN + (j - 1)];
        const int it1 = has2 ? neg_idx[b * KN + (j2 - 1)] : it0;

        const uint4* p0 = reinterpret_cast<const uint4*>(g_item_bf16 + (size_t)it0 * DN);
        const uint4* p1 = reinterpret_cast<const uint4*>(g_item_bf16 + (size_t)it1 * DN);

        // Issue all 6 gathers up front (MLP=6).
        uint4 a0 = __ldg(&p0[lane]);
        uint4 a1 = __ldg(&p0[32 + lane]);
        uint4 a2 = __ldg(&p0[64 + lane]);
        uint4 b0 = __ldg(&p1[lane]);
        uint4 b1 = __ldg(&p1[32 + lane]);
        uint4 b2 = __ldg(&p1[64 + lane]);

        float acc0 = 0.0f, acc1 = 0.0f;
        dot8(acc0, a0, uv[0], uv[1]);
        dot8(acc0, a1, uv[2], uv[3]);
        dot8(acc0, a2, uv[4], uv[5]);
        dot8(acc1, b0, uv[0], uv[1]);
        dot8(acc1, b1, uv[2], uv[3]);
        dot8(acc1, b2, uv[4], uv[5]);

        #pragma unroll
        for (int o = 16; o > 0; o >>= 1) {
            acc0 += __shfl_xor_sync(0xffffffffu, acc0, o);
            acc1 += __shfl_xor_sync(0xffffffffu, acc1, o);
        }
        if (lane == 0) {
            slog[j] = acc0;
            if (has2) slog[j2] = acc1;
        }
    }
    __syncthreads();

    // Warp 0: stable logsumexp over 61 logits (2 per lane).
    if (warp == 0) {
        const float l0 = slog[lane];
        const float l1 = slog[lane + 32];
        float m = fmaxf(l0, l1);
        #pragma unroll
        for (int o = 16; o > 0; o >>= 1)
            m = fmaxf(m, __shfl_xor_sync(0xffffffffu, m, o));
        float s = expf(l0 - m) + ((lane + 32 < NLOGITS) ? expf(l1 - m) : 0.0f);
        #pragma unroll
        for (int o = 16; o > 0; o >>= 1)
            s += __shfl_xor_sync(0xffffffffu, s, o);
        if (lane == 0) {
            g_row_loss[b] = logf(s) + m - slog[0];
            __threadfence();
            const int t = atomicAdd(&g_ctr, 1);
            s_last = (t == BN - 1);
        }
    }
    __syncthreads();

    // Last CTA: deterministic mean over all 4096 row losses.
    if (s_last) {
        __threadfence();
        __shared__ float sred[256];
        float a = 0.0f;
        #pragma unroll
        for (int i = tid; i < BN; i += 256) a += g_row_loss[i];
        sred[tid] = a;
        __syncthreads();
        #pragma unroll
        for (int st = 128; st > 0; st >>= 1) {
            if (tid < st) sred[tid] += sred[tid + st];
            __syncthreads();
        }
        if (tid == 0) {
            out[0] = sred[0] * (1.0f / (float)BN);
            g_ctr = 0;                                 // reset for next graph replay
        }
    }
}

extern "C" void kernel_launch(void* const* d_in, const int* in_sizes, int n_in,
                              void* d_out, int out_size)
{
    const float* user_emb = (const float*)d_in[0];
    const float* item_emb = (const float*)d_in[1];
    const int*   neg_idx  = (const int*)d_in[2];
    float*       out      = (float*)d_out;

    convert_items_kernel<<<BN * DN / 8 / 256, 256>>>(item_emb);
    u2i_loss_kernel<<<BN, 256>>>(user_emb, neg_idx, out);
}

// round 5
// speedup vs baseline: 1.4961x; 1.0091x over previous
#include <cuda_runtime.h>
#include <cuda_bf16.h>

// Problem constants (fixed by the reference).
#define BN 4096
#define DN 768
#define KN 60
#define NLOGITS 61   // [pos, 60 negs]

// Scratch (__device__ globals: no allocation allowed).
__device__ __nv_bfloat16 g_item_bf16[BN * DN];   // 6.3 MB bf16 mirror of item table
__device__ float g_row_loss[BN];
__device__ int   g_ctr = 0;

// ---------------------------------------------------------------------------
// Prologue: fp32 item table -> bf16 mirror. 8 floats per thread.
// ---------------------------------------------------------------------------
__global__ void __launch_bounds__(256)
convert_items_kernel(const float* __restrict__ item_emb)
{
    const int i = blockIdx.x * blockDim.x + threadIdx.x;   // 0 .. BN*DN/8-1
    const float4* src = reinterpret_cast<const float4*>(item_emb);
    const float4 a = src[2 * i];
    const float4 b = src[2 * i + 1];

    __nv_bfloat162 r[4];
    r[0] = __floats2bfloat162_rn(a.x, a.y);
    r[1] = __floats2bfloat162_rn(a.z, a.w);
    r[2] = __floats2bfloat162_rn(b.x, b.y);
    r[3] = __floats2bfloat162_rn(b.z, b.w);
    reinterpret_cast<uint4*>(g_item_bf16)[i] = *reinterpret_cast<uint4*>(r);
}

// 8 bf16 (uint4) dot fp32x8 (two float4) accumulated into fp32.
__device__ __forceinline__ void dot8(float& acc, const uint4& pv,
                                     const float4& uv0, const float4& uv1)
{
    const float2 f0 = __bfloat1622float2(*reinterpret_cast<const __nv_bfloat162*>(&pv.x));
    const float2 f1 = __bfloat1622float2(*reinterpret_cast<const __nv_bfloat162*>(&pv.y));
    const float2 f2 = __bfloat1622float2(*reinterpret_cast<const __nv_bfloat162*>(&pv.z));
    const float2 f3 = __bfloat1622float2(*reinterpret_cast<const __nv_bfloat162*>(&pv.w));
    acc = fmaf(f0.x, uv0.x, acc);
    acc = fmaf(f0.y, uv0.y, acc);
    acc = fmaf(f1.x, uv0.z, acc);
    acc = fmaf(f1.y, uv0.w, acc);
    acc = fmaf(f2.x, uv1.x, acc);
    acc = fmaf(f2.y, uv1.y, acc);
    acc = fmaf(f3.x, uv1.z, acc);
    acc = fmaf(f3.y, uv1.w, acc);
}

// ---------------------------------------------------------------------------
// Main: one CTA per user row; 8 warps split the 61 logits.
// User row lives in REGISTERS (no smem in the hot loop); two logits per
// iteration for 6-deep load parallelism.
// ---------------------------------------------------------------------------
__global__ void __launch_bounds__(256, 3)
u2i_loss_kernel(const float* __restrict__ user_emb,
                const int*   __restrict__ neg_idx,
                float*       __restrict__ out)
{
    __shared__ float su[DN];
    __shared__ float slog[64];        // 61 used, rest padded with -inf
    __shared__ int   s_last;

    const int b    = blockIdx.x;
    const int tid  = threadIdx.x;
    const int warp = tid >> 5;
    const int lane = tid & 31;

    // Stage user row coalesced into smem once, then lift this lane's slice
    // into registers (6 x float4 = 24 regs).
    const float4* u4  = reinterpret_cast<const float4*>(user_emb + (size_t)b * DN);
    float4*       su4 = reinterpret_cast<float4*>(su);
    if (tid < DN / 4) su4[tid] = u4[tid];
    if (tid >= 61 && tid < 64) slog[tid] = -3.0e38f;
    __syncthreads();

    float4 uv[6];
    #pragma unroll
    for (int t = 0; t < 3; ++t) {
        uv[2 * t]     = su4[2 * (t * 32 + lane)];
        uv[2 * t + 1] = su4[2 * (t * 32 + lane) + 1];
    }

    // Logit pairs (j, j+8): warps 0-4 do 4 pairs, warps 5-7 do 3 pairs + 1.
    for (int j = warp; j < NLOGITS; j += 16) {
        const int  j2   = j + 8;
        const bool has2 = (j2 < NLOGITS);

        const int it0 = (j == 0) ? b : neg_idx[b * KN + (j - 1)];
        const int it1 = has2 ? neg_idx[b * KN + (j2 - 1)] : it0;

        const uint4* p0 = reinterpret_cast<const uint4*>(g_item_bf16 + (size_t)it0 * DN);
        const uint4* p1 = reinterpret_cast<const uint4*>(g_item_bf16 + (size_t)it1 * DN);

        // Issue all 6 gathers up front (MLP=6).
        uint4 a0 = __ldg(&p0[lane]);
        uint4 a1 = __ldg(&p0[32 + lane]);
        uint4 a2 = __ldg(&p0[64 + lane]);
        uint4 b0 = __ldg(&p1[lane]);
        uint4 b1 = __ldg(&p1[32 + lane]);
        uint4 b2 = __ldg(&p1[64 + lane]);

        float acc0 = 0.0f, acc1 = 0.0f;
        dot8(acc0, a0, uv[0], uv[1]);
        dot8(acc0, a1, uv[2], uv[3]);
        dot8(acc0, a2, uv[4], uv[5]);
        dot8(acc1, b0, uv[0], uv[1]);
        dot8(acc1, b1, uv[2], uv[3]);
        dot8(acc1, b2, uv[4], uv[5]);

        #pragma unroll
        for (int o = 16; o > 0; o >>= 1) {
            acc0 += __shfl_xor_sync(0xffffffffu, acc0, o);
            acc1 += __shfl_xor_sync(0xffffffffu, acc1, o);
        }
        if (lane == 0) {
            slog[j] = acc0;
            if (has2) slog[j2] = acc1;
        }
    }
    __syncthreads();

    // Warp 0: stable logsumexp over 61 logits (2 per lane).
    if (warp == 0) {
        const float l0 = slog[lane];
        const float l1 = slog[lane + 32];
        float m = fmaxf(l0, l1);
        #pragma unroll
        for (int o = 16; o > 0; o >>= 1)
            m = fmaxf(m, __shfl_xor_sync(0xffffffffu, m, o));
        float s = expf(l0 - m) + ((lane + 32 < NLOGITS) ? expf(l1 - m) : 0.0f);
        #pragma unroll
        for (int o = 16; o > 0; o >>= 1)
            s += __shfl_xor_sync(0xffffffffu, s, o);
        if (lane == 0) {
            g_row_loss[b] = logf(s) + m - slog[0];
            __threadfence();
            const int t = atomicAdd(&g_ctr, 1);
            s_last = (t == BN - 1);
        }
    }
    __syncthreads();

    // Last CTA: deterministic mean over all 4096 row losses.
    if (s_last) {
        __threadfence();
        __shared__ float sred[256];
        float a = 0.0f;
        #pragma unroll
        for (int i = tid; i < BN; i += 256) a += g_row_loss[i];
        sred[tid] = a;
        __syncthreads();
        #pragma unroll
        for (int st = 128; st > 0; st >>= 1) {
            if (tid < st) sred[tid] += sred[tid + st];
            __syncthreads();
        }
        if (tid == 0) {
            out[0] = sred[0] * (1.0f / (float)BN);
            g_ctr = 0;                                 // reset for next graph replay
        }
    }
}

extern "C" void kernel_launch(void* const* d_in, const int* in_sizes, int n_in,
                              void* d_out, int out_size)
{
    const float* user_emb = (const float*)d_in[0];
    const float* item_emb = (const float*)d_in[1];
    const int*   neg_idx  = (const int*)d_in[2];
    float*       out      = (float*)d_out;

    convert_items_kernel<<<BN * DN / 8 / 256, 256>>>(item_emb);
    u2i_loss_kernel<<<BN, 256>>>(user_emb, neg_idx, out);
}